// round 3
// baseline (speedup 1.0000x reference)
#include <cuda_runtime.h>

typedef unsigned long long ull;

#define D_DIM   128
#define K_DIM   32
#define N_PIX   4096
#define B_SZ    8
#define TILE_T  128
#define XSTRIDE 130   // padded row stride for x tile (conflict-free f32/f32x2 in both phases)
#define ASTRIDE 132   // padded row stride for A/logits (float4-aligned, mild conflicts only in softmax)

// shared-memory layout (float offsets)
#define X_OFF    0
#define C_OFF    (TILE_T * XSTRIDE)                // 16640
#define A_OFF    (C_OFF + K_DIM * D_DIM)           // 20736
#define XSQ_OFF  (A_OFF + K_DIM * ASTRIDE)         // 24960
#define S_OFF    (XSQ_OFF + TILE_T)                // 25088
#define BK_OFF   (S_OFF + K_DIM)                   // 25120
#define WAS_OFF  (BK_OFF + K_DIM)                  // 25152
#define ASUM_OFF (WAS_OFF + 8 * K_DIM)             // 25408
#define SMEM_FLOATS (ASUM_OFF + K_DIM)             // 25440
#define SMEM_BYTES  (SMEM_FLOATS * 4)              // 101760 B

// packed fp32x2 FMA (Blackwell): acc.lo += a.lo*b.lo ; acc.hi += a.hi*b.hi
__device__ __forceinline__ void ffma2(ull &acc, ull a, ull b) {
    asm("fma.rn.f32x2 %0, %1, %2, %0;" : "+l"(acc) : "l"(a), "l"(b));
}
__device__ __forceinline__ float2 u2f(ull v) {
    float2 r;
    asm("mov.b64 {%0, %1}, %2;" : "=f"(r.x), "=f"(r.y) : "l"(v));
    return r;
}
__device__ __forceinline__ ull f2u(float x, float y) {
    ull v;
    asm("mov.b64 %0, {%1, %2};" : "=l"(v) : "f"(x), "f"(y));
    return v;
}

__global__ void zero_kernel(float* p, int n) {
    int i = blockIdx.x * blockDim.x + threadIdx.x;
    if (i < n) p[i] = 0.0f;
}

__global__ void __launch_bounds__(256, 2)
enc_kernel(const float* __restrict__ X,
           const float* __restrict__ CW,
           const float* __restrict__ SC,
           float* __restrict__ out)
{
    extern __shared__ float sm[];

    const int tid  = threadIdx.x;
    const int w    = tid >> 5;    // warp 0..7
    const int l    = tid & 31;    // lane
    const int b    = blockIdx.x >> 5;      // batch
    const int tile = blockIdx.x & 31;      // pixel tile within batch
    const int n0   = tile * TILE_T;

    // ---- load X tile [128 d][128 t] into x_sh[t][XSTRIDE], and codewords ----
    {
        const float* Xb = X + (size_t)b * D_DIM * N_PIX + n0;
        #pragma unroll
        for (int s = 0; s < 64; s++) {
            int idx = tid + 256 * s;           // 0 .. 16383
            int d = idx >> 7;
            int t = idx & 127;
            sm[X_OFF + t * XSTRIDE + d] = Xb[d * N_PIX + t];
        }
        #pragma unroll
        for (int s = 0; s < 16; s++) {
            int idx = tid + 256 * s;           // 0 .. 4095
            sm[C_OFF + idx] = CW[idx];
        }
    }
    __syncthreads();

    // ---- xsq per pixel: warp w handles rows [w*16, w*16+16) ----
    for (int p = 0; p < 16; p++) {
        int t = w * 16 + p;
        const float* row = sm + X_OFF + t * XSTRIDE;
        float2 v0 = *(const float2*)(row + 2 * l);
        float2 v1 = *(const float2*)(row + 64 + 2 * l);
        float ss = v0.x * v0.x + v0.y * v0.y + v1.x * v1.x + v1.y * v1.y;
        #pragma unroll
        for (int o = 16; o > 0; o >>= 1) ss += __shfl_xor_sync(0xffffffffu, ss, o);
        if (l == 0) sm[XSQ_OFF + t] = ss;
    }
    // ---- csq*scale and scale per codeword: warp w handles k = 4w..4w+3 ----
    for (int jj = 0; jj < 4; jj++) {
        int k = 4 * w + jj;
        const float* row = sm + C_OFF + k * D_DIM;
        float2 v0 = *(const float2*)(row + 2 * l);
        float2 v1 = *(const float2*)(row + 64 + 2 * l);
        float ss = v0.x * v0.x + v0.y * v0.y + v1.x * v1.x + v1.y * v1.y;
        #pragma unroll
        for (int o = 16; o > 0; o >>= 1) ss += __shfl_xor_sync(0xffffffffu, ss, o);
        if (l == 0) {
            float sc = SC[k];
            sm[S_OFF + k]  = sc;
            sm[BK_OFF + k] = ss * sc;
        }
    }
    __syncthreads();

    // ---- Stage A: cross GEMM, thread tile 4t x 4k, d-pair packed f32x2 ----
    {
        ull acc[16];
        #pragma unroll
        for (int z = 0; z < 16; z++) acc[z] = 0ULL;

        const float* xr = sm + X_OFF + l * XSTRIDE;     // t = l + 32*i
        const float* cr = sm + C_OFF + (4 * w) * D_DIM; // k = 4w + jj

        #pragma unroll 2
        for (int dp = 0; dp < 64; dp++) {
            ull xv0 = *(const ull*)(xr + 0 * 32 * XSTRIDE + 2 * dp);
            ull xv1 = *(const ull*)(xr + 1 * 32 * XSTRIDE + 2 * dp);
            ull xv2 = *(const ull*)(xr + 2 * 32 * XSTRIDE + 2 * dp);
            ull xv3 = *(const ull*)(xr + 3 * 32 * XSTRIDE + 2 * dp);
            ull cv0 = *(const ull*)(cr + 0 * D_DIM + 2 * dp);
            ull cv1 = *(const ull*)(cr + 1 * D_DIM + 2 * dp);
            ull cv2 = *(const ull*)(cr + 2 * D_DIM + 2 * dp);
            ull cv3 = *(const ull*)(cr + 3 * D_DIM + 2 * dp);
            ffma2(acc[0],  xv0, cv0); ffma2(acc[1],  xv0, cv1);
            ffma2(acc[2],  xv0, cv2); ffma2(acc[3],  xv0, cv3);
            ffma2(acc[4],  xv1, cv0); ffma2(acc[5],  xv1, cv1);
            ffma2(acc[6],  xv1, cv2); ffma2(acc[7],  xv1, cv3);
            ffma2(acc[8],  xv2, cv0); ffma2(acc[9],  xv2, cv1);
            ffma2(acc[10], xv2, cv2); ffma2(acc[11], xv2, cv3);
            ffma2(acc[12], xv3, cv0); ffma2(acc[13], xv3, cv1);
            ffma2(acc[14], xv3, cv2); ffma2(acc[15], xv3, cv3);
        }

        // logits = scale_k * (xsq_t - 2*cross + csq_k) -> A_sh[k][t]
        #pragma unroll
        for (int i = 0; i < 4; i++) {
            int t = l + 32 * i;
            float xsq = sm[XSQ_OFF + t];
            #pragma unroll
            for (int jj = 0; jj < 4; jj++) {
                int k = 4 * w + jj;
                float2 pr = u2f(acc[i * 4 + jj]);
                float cross = pr.x + pr.y;
                float lg = fmaf(sm[S_OFF + k], fmaf(-2.0f, cross, xsq), sm[BK_OFF + k]);
                sm[A_OFF + k * ASTRIDE + t] = lg;
            }
        }
    }
    __syncthreads();

    // ---- Softmax over k (lane = k): warp w handles pixels [w*16, w*16+16) ----
    {
        float asum_l = 0.0f;
        for (int p = 0; p < 16; p++) {
            int t = w * 16 + p;
            float v = sm[A_OFF + l * ASTRIDE + t];
            float m = v;
            #pragma unroll
            for (int o = 16; o > 0; o >>= 1) m = fmaxf(m, __shfl_xor_sync(0xffffffffu, m, o));
            float e = __expf(v - m);
            float s = e;
            #pragma unroll
            for (int o = 16; o > 0; o >>= 1) s += __shfl_xor_sync(0xffffffffu, s, o);
            float a = e * __fdividef(1.0f, s);
            sm[A_OFF + l * ASTRIDE + t] = a;
            asum_l += a;
        }
        sm[WAS_OFF + w * 32 + l] = asum_l;
    }
    __syncthreads();
    if (tid < 32) {
        float a = 0.0f;
        #pragma unroll
        for (int ww = 0; ww < 8; ww++) a += sm[WAS_OFF + ww * 32 + tid];
        sm[ASUM_OFF + tid] = a;
    }
    __syncthreads();

    // ---- Stage B: E[k][d] += sum_t A[t][k] * x[t][d], pixel-pair packed ----
    {
        const int g = tid >> 7;        // pixel half: [0,64) or [64,128)
        const int d = tid & 127;

        ull acc2[32];
        #pragma unroll
        for (int k = 0; k < 32; k++) acc2[k] = 0ULL;

        const float* xcol = sm + X_OFF + d;
        const int tbase = g * 64;

        for (int q = 0; q < 16; q++) {          // 16 quads = 64 pixels
            int t = tbase + q * 4;
            float x0 = xcol[(t + 0) * XSTRIDE];
            float x1 = xcol[(t + 1) * XSTRIDE];
            float x2 = xcol[(t + 2) * XSTRIDE];
            float x3 = xcol[(t + 3) * XSTRIDE];
            ull xv01 = f2u(x0, x1);
            ull xv23 = f2u(x2, x3);
            const float* Ab = sm + A_OFF + t;
            #pragma unroll
            for (int k = 0; k < 32; k++) {
                float4 a = *(const float4*)(Ab + k * ASTRIDE);   // broadcast LDS.128
                ffma2(acc2[k], f2u(a.x, a.y), xv01);
                ffma2(acc2[k], f2u(a.z, a.w), xv23);
            }
        }

        // fold -Asum[k]*c[k][d] once (group 0 only) and merge across blocks
        float* Eb = out + (size_t)b * K_DIM * D_DIM + d;
        #pragma unroll
        for (int k = 0; k < 32; k++) {
            float2 pr = u2f(acc2[k]);
            float v = pr.x + pr.y;
            if (g == 0) v = fmaf(-sm[ASUM_OFF + k], sm[C_OFF + k * D_DIM + d], v);
            atomicAdd(Eb + k * D_DIM, v);
        }
    }
}

extern "C" void kernel_launch(void* const* d_in, const int* in_sizes, int n_in,
                              void* d_out, int out_size)
{
    const float* X  = (const float*)d_in[0];
    const float* CW = (const float*)d_in[1];
    const float* SC = (const float*)d_in[2];
    float* out = (float*)d_out;

    cudaFuncSetAttribute(enc_kernel, cudaFuncAttributeMaxDynamicSharedMemorySize, SMEM_BYTES);

    const int OUT_N = B_SZ * K_DIM * D_DIM;           // 32768
    zero_kernel<<<(OUT_N + 255) / 256, 256>>>(out, OUT_N);
    enc_kernel<<<B_SZ * (N_PIX / TILE_T), 256, SMEM_BYTES>>>(X, CW, SC, out);
}

// round 4
// speedup vs baseline: 1.0359x; 1.0359x over previous
#include <cuda_runtime.h>

typedef unsigned long long ull;

#define D_DIM   128
#define K_DIM   32
#define N_PIX   4096
#define B_SZ    8
#define TILE_T  128
#define XSTRIDE 130   // padded row stride for x tile (conflict-free f32/f32x2 in both phases)
#define ASTRIDE 132   // padded row stride for A/logits (float4-aligned, mild conflicts only in softmax)

// shared-memory layout (float offsets)
#define X_OFF    0
#define C_OFF    (TILE_T * XSTRIDE)                // 16640
#define A_OFF    (C_OFF + K_DIM * D_DIM)           // 20736
#define XSQ_OFF  (A_OFF + K_DIM * ASTRIDE)         // 24960
#define S_OFF    (XSQ_OFF + TILE_T)                // 25088
#define BK_OFF   (S_OFF + K_DIM)                   // 25120
#define WAS_OFF  (BK_OFF + K_DIM)                  // 25152
#define ASUM_OFF (WAS_OFF + 8 * K_DIM)             // 25408
#define SMEM_FLOATS (ASUM_OFF + K_DIM)             // 25440
#define SMEM_BYTES  (SMEM_FLOATS * 4)              // 101760 B

// packed fp32x2 FMA (Blackwell): acc.lo += a.lo*b.lo ; acc.hi += a.hi*b.hi
__device__ __forceinline__ void ffma2(ull &acc, ull a, ull b) {
    asm("fma.rn.f32x2 %0, %1, %2, %0;" : "+l"(acc) : "l"(a), "l"(b));
}
__device__ __forceinline__ float2 u2f(ull v) {
    float2 r;
    asm("mov.b64 {%0, %1}, %2;" : "=f"(r.x), "=f"(r.y) : "l"(v));
    return r;
}
__device__ __forceinline__ ull f2u(float x, float y) {
    ull v;
    asm("mov.b64 %0, {%1, %2};" : "=l"(v) : "f"(x), "f"(y));
    return v;
}

__global__ void zero_kernel(float* p, int n) {
    int i = blockIdx.x * blockDim.x + threadIdx.x;
    if (i < n) p[i] = 0.0f;
}

__global__ void __launch_bounds__(256, 2)
enc_kernel(const float* __restrict__ X,
           const float* __restrict__ CW,
           const float* __restrict__ SC,
           float* __restrict__ out)
{
    extern __shared__ float sm[];

    const int tid  = threadIdx.x;
    const int w    = tid >> 5;    // warp 0..7
    const int l    = tid & 31;    // lane
    const int b    = blockIdx.x >> 5;      // batch
    const int tile = blockIdx.x & 31;      // pixel tile within batch
    const int n0   = tile * TILE_T;

    // ---- load X tile [128 d][128 t] into x_sh[t][XSTRIDE], and codewords ----
    {
        const float* Xb = X + (size_t)b * D_DIM * N_PIX + n0;
        #pragma unroll
        for (int s = 0; s < 64; s++) {
            int idx = tid + 256 * s;           // 0 .. 16383
            int d = idx >> 7;
            int t = idx & 127;
            sm[X_OFF + t * XSTRIDE + d] = Xb[d * N_PIX + t];
        }
        #pragma unroll
        for (int s = 0; s < 16; s++) {
            int idx = tid + 256 * s;           // 0 .. 4095
            sm[C_OFF + idx] = CW[idx];
        }
    }
    __syncthreads();

    // ---- xsq per pixel: warp w handles rows [w*16, w*16+16) ----
    for (int p = 0; p < 16; p++) {
        int t = w * 16 + p;
        const float* row = sm + X_OFF + t * XSTRIDE;
        float2 v0 = *(const float2*)(row + 2 * l);
        float2 v1 = *(const float2*)(row + 64 + 2 * l);
        float ss = v0.x * v0.x + v0.y * v0.y + v1.x * v1.x + v1.y * v1.y;
        #pragma unroll
        for (int o = 16; o > 0; o >>= 1) ss += __shfl_xor_sync(0xffffffffu, ss, o);
        if (l == 0) sm[XSQ_OFF + t] = ss;
    }
    // ---- csq*scale and scale per codeword: warp w handles k = 4w..4w+3 ----
    for (int jj = 0; jj < 4; jj++) {
        int k = 4 * w + jj;
        const float* row = sm + C_OFF + k * D_DIM;
        float2 v0 = *(const float2*)(row + 2 * l);
        float2 v1 = *(const float2*)(row + 64 + 2 * l);
        float ss = v0.x * v0.x + v0.y * v0.y + v1.x * v1.x + v1.y * v1.y;
        #pragma unroll
        for (int o = 16; o > 0; o >>= 1) ss += __shfl_xor_sync(0xffffffffu, ss, o);
        if (l == 0) {
            float sc = SC[k];
            sm[S_OFF + k]  = sc;
            sm[BK_OFF + k] = ss * sc;
        }
    }
    __syncthreads();

    // ---- Stage A: cross GEMM, thread tile 4t x 4k, d-pair packed f32x2 ----
    {
        ull acc[16];
        #pragma unroll
        for (int z = 0; z < 16; z++) acc[z] = 0ULL;

        const float* xr = sm + X_OFF + l * XSTRIDE;     // t = l + 32*i
        const float* cr = sm + C_OFF + (4 * w) * D_DIM; // k = 4w + jj

        #pragma unroll 2
        for (int dp = 0; dp < 64; dp++) {
            ull xv0 = *(const ull*)(xr + 0 * 32 * XSTRIDE + 2 * dp);
            ull xv1 = *(const ull*)(xr + 1 * 32 * XSTRIDE + 2 * dp);
            ull xv2 = *(const ull*)(xr + 2 * 32 * XSTRIDE + 2 * dp);
            ull xv3 = *(const ull*)(xr + 3 * 32 * XSTRIDE + 2 * dp);
            ull cv0 = *(const ull*)(cr + 0 * D_DIM + 2 * dp);
            ull cv1 = *(const ull*)(cr + 1 * D_DIM + 2 * dp);
            ull cv2 = *(const ull*)(cr + 2 * D_DIM + 2 * dp);
            ull cv3 = *(const ull*)(cr + 3 * D_DIM + 2 * dp);
            ffma2(acc[0],  xv0, cv0); ffma2(acc[1],  xv0, cv1);
            ffma2(acc[2],  xv0, cv2); ffma2(acc[3],  xv0, cv3);
            ffma2(acc[4],  xv1, cv0); ffma2(acc[5],  xv1, cv1);
            ffma2(acc[6],  xv1, cv2); ffma2(acc[7],  xv1, cv3);
            ffma2(acc[8],  xv2, cv0); ffma2(acc[9],  xv2, cv1);
            ffma2(acc[10], xv2, cv2); ffma2(acc[11], xv2, cv3);
            ffma2(acc[12], xv3, cv0); ffma2(acc[13], xv3, cv1);
            ffma2(acc[14], xv3, cv2); ffma2(acc[15], xv3, cv3);
        }

        // logits = scale_k * (xsq_t - 2*cross + csq_k) -> A_sh[k][t]
        #pragma unroll
        for (int i = 0; i < 4; i++) {
            int t = l + 32 * i;
            float xsq = sm[XSQ_OFF + t];
            #pragma unroll
            for (int jj = 0; jj < 4; jj++) {
                int k = 4 * w + jj;
                float2 pr = u2f(acc[i * 4 + jj]);
                float cross = pr.x + pr.y;
                float lg = fmaf(sm[S_OFF + k], fmaf(-2.0f, cross, xsq), sm[BK_OFF + k]);
                sm[A_OFF + k * ASTRIDE + t] = lg;
            }
        }
    }
    __syncthreads();

    // ---- Softmax over k (lane = k): warp w handles pixels [w*16, w*16+16) ----
    {
        float asum_l = 0.0f;
        for (int p = 0; p < 16; p++) {
            int t = w * 16 + p;
            float v = sm[A_OFF + l * ASTRIDE + t];
            float m = v;
            #pragma unroll
            for (int o = 16; o > 0; o >>= 1) m = fmaxf(m, __shfl_xor_sync(0xffffffffu, m, o));
            float e = __expf(v - m);
            float s = e;
            #pragma unroll
            for (int o = 16; o > 0; o >>= 1) s += __shfl_xor_sync(0xffffffffu, s, o);
            float a = e * __fdividef(1.0f, s);
            sm[A_OFF + l * ASTRIDE + t] = a;
            asum_l += a;
        }
        sm[WAS_OFF + w * 32 + l] = asum_l;
    }
    __syncthreads();
    if (tid < 32) {
        float a = 0.0f;
        #pragma unroll
        for (int ww = 0; ww < 8; ww++) a += sm[WAS_OFF + ww * 32 + tid];
        sm[ASUM_OFF + tid] = a;
    }
    __syncthreads();

    // ---- Stage B: E[k][d] += sum_t A[t][k] * x[t][d], pixel-pair packed ----
    {
        const int g = tid >> 7;        // pixel half: [0,64) or [64,128)
        const int d = tid & 127;

        ull acc2[32];
        #pragma unroll
        for (int k = 0; k < 32; k++) acc2[k] = 0ULL;

        const float* xcol = sm + X_OFF + d;
        const int tbase = g * 64;

        for (int q = 0; q < 16; q++) {          // 16 quads = 64 pixels
            int t = tbase + q * 4;
            float x0 = xcol[(t + 0) * XSTRIDE];
            float x1 = xcol[(t + 1) * XSTRIDE];
            float x2 = xcol[(t + 2) * XSTRIDE];
            float x3 = xcol[(t + 3) * XSTRIDE];
            ull xv01 = f2u(x0, x1);
            ull xv23 = f2u(x2, x3);
            const float* Ab = sm + A_OFF + t;
            #pragma unroll
            for (int k = 0; k < 32; k++) {
                float4 a = *(const float4*)(Ab + k * ASTRIDE);   // broadcast LDS.128
                ffma2(acc2[k], f2u(a.x, a.y), xv01);
                ffma2(acc2[k], f2u(a.z, a.w), xv23);
            }
        }

        // fold -Asum[k]*c[k][d] once (group 0 only) and merge across blocks
        float* Eb = out + (size_t)b * K_DIM * D_DIM + d;
        #pragma unroll
        for (int k = 0; k < 32; k++) {
            float2 pr = u2f(acc2[k]);
            float v = pr.x + pr.y;
            if (g == 0) v = fmaf(-sm[ASUM_OFF + k], sm[C_OFF + k * D_DIM + d], v);
            atomicAdd(Eb + k * D_DIM, v);
        }
    }
}

extern "C" void kernel_launch(void* const* d_in, const int* in_sizes, int n_in,
                              void* d_out, int out_size)
{
    const float* X  = (const float*)d_in[0];
    const float* CW = (const float*)d_in[1];
    const float* SC = (const float*)d_in[2];
    float* out = (float*)d_out;

    cudaFuncSetAttribute(enc_kernel, cudaFuncAttributeMaxDynamicSharedMemorySize, SMEM_BYTES);

    const int OUT_N = B_SZ * K_DIM * D_DIM;           // 32768
    zero_kernel<<<(OUT_N + 255) / 256, 256>>>(out, OUT_N);
    enc_kernel<<<B_SZ * (N_PIX / TILE_T), 256, SMEM_BYTES>>>(X, CW, SC, out);
}